// round 6
// baseline (speedup 1.0000x reference)
#include <cuda_runtime.h>

// out[r, c] = x[r, c] * weight[c]   for x: [32768, 1024] fp32, weight: [1024] fp32
//
// R6: persistent single-wave kernel. 740 CTAs = 148 SMs x 5 resident
// (reg-limited: 48 regs x 256 thr = 12.3K regs/CTA, 65536/CTA-regs = 5.33).
// All CTAs live for the whole kernel: zero wave transitions, zero repeated
// prologues, imbalance <= 1 chunk (2048 float4 ~ 32 KB ~ 0.5%).
// Body is the proven R2 shape: 8x float4 front-batched streaming loads,
// hoisted per-thread weight vector, streaming stores.

static constexpr int ROWS = 32768;
static constexpr int COLS = 1024;
static constexpr unsigned N_VEC4 = (unsigned)ROWS * (COLS / 4);    // 8,388,608
static constexpr int THREADS = 256;
static constexpr int VEC_PER_THREAD = 8;
static constexpr unsigned CHUNK_VEC4 = THREADS * VEC_PER_THREAD;   // 2048
static constexpr unsigned N_CHUNKS = N_VEC4 / CHUNK_VEC4;          // 4096
static constexpr int BLOCKS = 740;                                 // 148 SMs x 5
static constexpr int COLS_VEC4 = COLS / 4;                         // 256
static_assert(THREADS == COLS_VEC4, "weight-hoist relies on THREADS == COLS/4");
static_assert(N_CHUNKS * CHUNK_VEC4 == N_VEC4, "exact cover");

__global__ __launch_bounds__(THREADS)
void diag_weight_kernel(const float4* __restrict__ x,
                        const float4* __restrict__ w,
                        float4* __restrict__ out) {
    const unsigned tid = threadIdx.x;

    // Chunk bases are multiples of 2048, so every index this thread touches
    // is congruent to tid (mod 256): one cached weight load for all chunks.
    const float4 vw = w[tid];

    // Persistent grid-stride over chunks; outer loop NOT unrolled so the
    // live set stays one chunk's worth (regs ~48-56, 5 CTAs/SM resident).
    for (unsigned c = blockIdx.x; c < N_CHUNKS; c += (unsigned)BLOCKS) {
        const unsigned base = c * CHUNK_VEC4 + tid;

        float4 vx[VEC_PER_THREAD];

        // Front-batch all 8 streaming loads (MLP burst = 8 per thread).
#pragma unroll
        for (int i = 0; i < VEC_PER_THREAD; i++) {
            vx[i] = __ldcs(&x[base + (unsigned)i * THREADS]);
        }

#pragma unroll
        for (int i = 0; i < VEC_PER_THREAD; i++) {
            float4 r;
            r.x = vx[i].x * vw.x;
            r.y = vx[i].y * vw.y;
            r.z = vx[i].z * vw.z;
            r.w = vx[i].w * vw.w;
            __stcs(&out[base + (unsigned)i * THREADS], r);
        }
    }
}

extern "C" void kernel_launch(void* const* d_in, const int* in_sizes, int n_in,
                              void* d_out, int out_size) {
    const float4* x = (const float4*)d_in[0];   // [32768, 1024] fp32
    const float4* w = (const float4*)d_in[1];   // [1024] fp32
    float4* out = (float4*)d_out;

    diag_weight_kernel<<<BLOCKS, THREADS>>>(x, w, out);
}